// round 14
// baseline (speedup 1.0000x reference)
#include <cuda_runtime.h>
#include <cuda_bf16.h>
#include <stdint.h>
#include <math.h>
#include <string.h>

#define BN 64
#define TT 32
#define HD 1024
#define LL 196
#define LT 28            // attention tile rows
#define GRID 128

// ---------------- device scratch --------------------------------------------
__device__ uint4 g_w0p[(size_t)4096 * 256];      // w_ih1 (K=1024), for X1
__device__ uint4 g_w1p[(size_t)4096 * 256];      // w_hh1 (K=1024), cell1
__device__ uint4 g_wcat[(size_t)4096 * 768];     // [w_ih2 | w_hh2] (K=3072), cell2
__device__ uint4 g_cat[2][(size_t)BN * 768];     // [vatt | h1 | h2] A-records
__device__ uint4 g_xp[(size_t)2048 * 256];       // embedded inputs (K=1024 records)
__device__ float g_X1p[(size_t)2048 * 4096];     // x@w_ih1^T + biases (fp32, permuted)
__device__ float g_h1f[BN * HD];
__device__ float g_c1[BN * HD], g_c2[BN * HD];
__device__ float g_bs1[4096], g_bs2[4096];
__device__ int   g_bar_count;

__device__ __forceinline__ float sigf(float x) { return 1.0f / (1.0f + expf(-x)); }

__device__ __forceinline__ uint32_t bfbits(__nv_bfloat16 h) {
    unsigned short s; memcpy(&s, &h, 2); return (uint32_t)s;
}

__device__ __forceinline__ int pair_slot(int p) {
    int ks = p >> 3, w = p & 7;
    return ks * 8 + ((w & 3) << 1) + (w >> 2);
}

__device__ __forceinline__ void split2(float2 v, uint32_t& hi, uint32_t& lo) {
    __nv_bfloat16 h0 = __float2bfloat16(v.x);
    __nv_bfloat16 h1 = __float2bfloat16(v.y);
    __nv_bfloat16 l0 = __float2bfloat16(v.x - __bfloat162float(h0));
    __nv_bfloat16 l1 = __float2bfloat16(v.y - __bfloat162float(h1));
    hi = bfbits(h0) | (bfbits(h1) << 16);
    lo = bfbits(l0) | (bfbits(l1) << 16);
}

__device__ __forceinline__ void mma_bf16(float c[4],
    uint32_t a0, uint32_t a1, uint32_t a2, uint32_t a3,
    uint32_t b0, uint32_t b1)
{
    asm volatile(
        "mma.sync.aligned.m16n8k16.row.col.f32.bf16.bf16.f32 "
        "{%0,%1,%2,%3}, {%4,%5,%6,%7}, {%8,%9}, {%0,%1,%2,%3};"
        : "+f"(c[0]), "+f"(c[1]), "+f"(c[2]), "+f"(c[3])
        : "r"(a0), "r"(a1), "r"(a2), "r"(a3), "r"(b0), "r"(b1));
}

// ---------------- software grid barrier (all 128 blocks resident) -----------
__device__ __forceinline__ void grid_bar(int target) {
    __syncthreads();
    if (threadIdx.x == 0) {
        __threadfence();
        atomicAdd(&g_bar_count, 1);
        while (*(volatile int*)&g_bar_count < target) __nanosleep(64);
    }
    __syncthreads();
}

// ---------------- setup #0: all weight conversion ---------------------------
__device__ __forceinline__ void conv_one(const float* __restrict__ w,
                                         uint2* __restrict__ dst,
                                         int Kw, int lg,
                                         int dst_pit2, int ks_off2, int idx) {
    int j  = idx >> lg;
    int kp = idx & ((1 << lg) - 1);
    int src = (j & 3) * 1024 + (j >> 2);               // gate-interleave perm
    float v0 = w[(size_t)src * Kw + 2 * kp];
    float v1 = w[(size_t)src * Kw + 2 * kp + 1];
    uint32_t hi, lo;
    split2(make_float2(v0, v1), hi, lo);
    int ks = kp >> 3, qp = kp & 3, half = (kp >> 2) & 1;
    dst[(size_t)j * dst_pit2 + ks_off2 + ks * 8 + qp * 2 + half] = make_uint2(hi, lo);
}

__global__ __launch_bounds__(256) void setup_w(
    const float* __restrict__ w_ih1, const float* __restrict__ w_hh1,
    const float* __restrict__ w_ih2, const float* __restrict__ w_hh2)
{
    int b = blockIdx.x, tid = threadIdx.x;
    if (b < 8192)
        conv_one(w_ih1, (uint2*)g_w0p, 1024, 9, 512, 0, b * 256 + tid);
    else if (b < 16384)
        conv_one(w_hh1, (uint2*)g_w1p, 1024, 9, 512, 0, (b - 8192) * 256 + tid);
    else if (b < 32768)
        conv_one(w_ih2, (uint2*)g_wcat, 2048, 10, 1536, 0, (b - 16384) * 256 + tid);
    else
        conv_one(w_hh2, (uint2*)g_wcat, 1024, 9, 1536, 1024, (b - 32768) * 256 + tid);
}

// ---------------- setup #1: zero, bias prep, gather+split, barrier reset ----
__global__ __launch_bounds__(256) void setup_misc(
    const int* __restrict__ inp, const float* __restrict__ emb,
    const float* __restrict__ b_ih1, const float* __restrict__ b_hh1,
    const float* __restrict__ b_ih2, const float* __restrict__ b_hh2)
{
    int b = blockIdx.x, tid = threadIdx.x;
    if (b == 0 && tid == 0) g_bar_count = 0;
    if (b < 384) {
        int i = b * 256 + tid;
        ((uint4*)g_cat)[i] = make_uint4(0u, 0u, 0u, 0u);
    } else if (b < 512) {
        int i = (b - 384) * 256 + tid;
        if (i < 16384) ((float4*)g_c1)[i] = make_float4(0.f, 0.f, 0.f, 0.f);
        else ((float4*)g_c2)[i - 16384] = make_float4(0.f, 0.f, 0.f, 0.f);
    } else if (b < 528) {
        int j = (b - 512) * 256 + tid;
        if (j < 4096) {
            int src = (j & 3) * 1024 + (j >> 2);
            g_bs1[j] = b_ih1[src] + b_hh1[src];
            g_bs2[j] = b_ih2[src] + b_hh2[src];
        }
    } else {
        int idx = (b - 528) * 256 + tid;
        int row = idx >> 9;
        int p   = idx & 511;
        int tok = inp[row];
        float v0 = emb[(size_t)tok * 1024 + 2 * p];
        float v1 = emb[(size_t)tok * 1024 + 2 * p + 1];
        uint32_t hi, lo;
        split2(make_float2(v0, v1), hi, lo);
        ((uint2*)g_xp)[(size_t)row * 512 + pair_slot(p)] = make_uint2(hi, lo);
    }
}

// ---------------- X1 GEMM: block tile m128 x n128 (3x less L2 traffic) ------
// 1024 threads = 32 warps = 8 m-warps x 4 n-warps; warp tile m16 x n32.
// grid (32 col-tiles, 16 row-tiles) = 512 blocks.
// Per-output summation order identical to previous version (bitwise same).
__global__ __launch_bounds__(1024) void mma_x1() {
    const int lane = threadIdx.x & 31;
    const int warp = threadIdx.x >> 5;
    const int wm   = warp >> 2;          // 0..7
    const int wn   = warp & 3;           // 0..3
    const int slab = blockIdx.x * 128 + wn * 32;
    const int r_lo = blockIdx.y * 128 + wm * 16 + (lane >> 2);
    const int qpair = lane & 3;
    const int qk = qpair * 2;
    const int qp = lane & 3;

    float c[4][4] = {};

    const uint4* A0 = g_xp + (size_t)r_lo * 256;
    const uint4* A1 = g_xp + (size_t)(r_lo + 8) * 256;

    for (int ks = 0; ks < 64; ks++) {
        uint4 q0 = A0[ks * 4 + qpair];
        uint4 q1 = A1[ks * 4 + qpair];
        #pragma unroll
        for (int tl = 0; tl < 4; tl++) {
            int j = slab + tl * 8 + (lane >> 2);
            uint4 B = g_w0p[(size_t)j * 256 + ks * 4 + qp];
            mma_bf16(c[tl], q0.x, q1.x, q0.z, q1.z, B.x, B.z);
            mma_bf16(c[tl], q0.x, q1.x, q0.z, q1.z, B.y, B.w);
            mma_bf16(c[tl], q0.y, q1.y, q0.w, q1.w, B.x, B.z);
        }
    }

    #pragma unroll
    for (int tl = 0; tl < 4; tl++) {
        int j0 = slab + tl * 8 + qk;
        float2 bs = *(const float2*)(g_bs1 + j0);
        *(float2*)(g_X1p + (size_t)r_lo * 4096 + j0) =
            make_float2(c[tl][0] + bs.x, c[tl][1] + bs.y);
        *(float2*)(g_X1p + (size_t)(r_lo + 8) * 4096 + j0) =
            make_float2(c[tl][2] + bs.x, c[tl][3] + bs.y);
    }
}

// ---------------- cell phase (device fn, inside persistent kernel) ----------
__device__ __forceinline__ void cell_phase(
    int mode, int t,
    const uint4* __restrict__ A, int a_pit,
    const uint4* __restrict__ W, int w_pit, int nits,
    uint2* __restrict__ hout, int h_pit,
    float* __restrict__ c_state, float* __restrict__ fout,
    float* red)
{
    #define RED(ksl, wr, ln, a) red[(((ksl) * 4 + (wr)) * 32 + (ln)) * 17 + (a)]
    const int lane   = threadIdx.x & 31;
    const int warp   = threadIdx.x >> 5;
    const int kslice = warp >> 2;
    const int wr     = warp & 3;
    const int slab   = blockIdx.x * 32;
    const int r_lo   = wr * 16 + (lane >> 2);
    const int qpair  = lane & 3;
    const int qk = qpair * 2;
    const int qp = lane & 3;

    float c[4][4] = {};

    const uint4* A0 = A + (size_t)r_lo * a_pit;
    const uint4* A1 = A + (size_t)(r_lo + 8) * a_pit;
    const int ks0 = kslice * nits;

    #pragma unroll 4
    for (int it = 0; it < nits; it++) {
        const int ks = ks0 + it;
        uint4 q0 = __ldcg(&A0[ks * 4 + qpair]);
        uint4 q1 = __ldcg(&A1[ks * 4 + qpair]);
        #pragma unroll
        for (int tl = 0; tl < 4; tl++) {
            int j = slab + tl * 8 + (lane >> 2);
            uint4 B = W[(size_t)j * w_pit + ks * 4 + qp];
            mma_bf16(c[tl], q0.x, q1.x, q0.z, q1.z, B.x, B.z);
            mma_bf16(c[tl], q0.x, q1.x, q0.z, q1.z, B.y, B.w);
            mma_bf16(c[tl], q0.y, q1.y, q0.w, q1.w, B.x, B.z);
        }
    }

    __syncthreads();
    #pragma unroll
    for (int tl = 0; tl < 4; tl++)
        #pragma unroll
        for (int i = 0; i < 4; i++)
            RED(kslice, wr, lane, tl * 4 + i) = c[tl][i];
    __syncthreads();

    if (warp < 4) {
        #pragma unroll
        for (int tl = 0; tl < 4; tl++)
            #pragma unroll
            for (int i = 0; i < 4; i++) {
                float v = 0.f;
                #pragma unroll
                for (int ksl = 0; ksl < 8; ksl++)
                    v += RED(ksl, wr, lane, tl * 4 + i);
                c[tl][i] = v;
            }

        const bool has_if = ((lane & 1) == 0);
        const int d = (slab >> 2);
        const int pbase = blockIdx.x * 4;

        #pragma unroll
        for (int tl = 0; tl < 4; tl++) {
            int j0 = slab + tl * 8 + qk;
            float x0, x1, x2, x3;
            if (mode == 1) {
                const float* x1p = g_X1p + (size_t)(t * 64 + r_lo) * 4096 + j0;
                float2 aL = *(const float2*)x1p;
                float2 aH = *(const float2*)(x1p + 8 * 4096);
                x0 = c[tl][0] + aL.x; x1 = c[tl][1] + aL.y;
                x2 = c[tl][2] + aH.x; x3 = c[tl][3] + aH.y;
            } else {
                float2 bs = *(const float2*)(g_bs2 + j0);
                x0 = c[tl][0] + bs.x; x1 = c[tl][1] + bs.y;
                x2 = c[tl][2] + bs.x; x3 = c[tl][3] + bs.y;
            }
            float y0 = __shfl_xor_sync(0xffffffffu, x0, 1);
            float y1 = __shfl_xor_sync(0xffffffffu, x1, 1);
            float y2 = __shfl_xor_sync(0xffffffffu, x2, 1);
            float y3 = __shfl_xor_sync(0xffffffffu, x3, 1);

            if (has_if) {
                int dd = d + tl * 2 + ((lane & 3) >> 1);
                int pair = pbase + tl;
                #pragma unroll
                for (int rr = 0; rr < 2; rr++) {
                    float iv = rr ? x2 : x0;
                    float fv = rr ? x3 : x1;
                    float gv = rr ? y2 : y0;
                    float ov = rr ? y3 : y1;
                    int n = r_lo + rr * 8;
                    int idx = n * 1024 + dd;
                    float ig = sigf(iv), fg = sigf(fv);
                    float gg = tanhf(gv), og = sigf(ov);
                    float cn = fg * c_state[idx] + ig * gg;
                    c_state[idx] = cn;
                    float hn = og * tanhf(cn);
                    __nv_bfloat16 hh = __float2bfloat16(hn);
                    uint32_t hib = bfbits(hh);
                    uint32_t lob = bfbits(__float2bfloat16(hn - __bfloat162float(hh)));
                    uint32_t myv = hib | (lob << 16);
                    uint32_t ov2 = __shfl_xor_sync(0x55555555u, myv, 2);
                    if ((lane & 3) == 0) {
                        uint2 w;
                        w.x = (myv & 0xffffu) | ((ov2 & 0xffffu) << 16);
                        w.y = (myv >> 16) | (ov2 & 0xffff0000u);
                        hout[(size_t)n * h_pit + pair_slot(pair)] = w;
                    }
                    if (mode == 1) fout[idx] = hn;
                    else fout[(size_t)(t * 64 + n) * 1024 + dd] = hn;
                }
            }
        }
    }
    #undef RED
}

// ---------------- attention phase (block pair: n = bid>>1, d-half = bid&1) --
__device__ __forceinline__ void attn_phase(const float* __restrict__ img,
                                           uint2* __restrict__ vout,
                                           float* smem)
{
    float* Fs  = smem;                 // LT * 1024
    float* h1s = smem + LT * 1024;     // 1024
    float* alf = h1s + 1024;           // LT

    const int n    = blockIdx.x >> 1;
    const int half = blockIdx.x & 1;
    const int tid  = threadIdx.x;
    const int w    = tid >> 5;
    const int lane = tid & 31;

    h1s[tid] = __ldcg(&g_h1f[(size_t)n * 1024 + tid]);

    const float4* base = (const float4*)(img + (size_t)n * LL * 1024);

    float4 stage[7];
    #pragma unroll
    for (int u = 0; u < 7; u++)
        stage[u] = base[tid + 1024 * u];

    float2 vacc = make_float2(0.f, 0.f);
    __syncthreads();

    for (int tb = 0; tb < LL; tb += LT) {
        #pragma unroll
        for (int u = 0; u < 7; u++)
            ((float4*)Fs)[tid + 1024 * u] = stage[u];
        __syncthreads();

        if (tb + LT < LL) {
            const float4* nb = base + (size_t)(tb + LT) * 256;
            #pragma unroll
            for (int u = 0; u < 7; u++)
                stage[u] = nb[tid + 1024 * u];
        }

        if (w < LT) {
            const float* f = Fs + w * 1024;
            float s = 0.f;
            #pragma unroll
            for (int i = 0; i < 8; i++) {
                int dd = i * 128 + lane * 4;
                float4 fv = *(const float4*)(f + dd);
                s += fv.x * h1s[dd] + fv.y * h1s[dd + 1]
                   + fv.z * h1s[dd + 2] + fv.w * h1s[dd + 3];
            }
            #pragma unroll
            for (int off = 16; off; off >>= 1)
                s += __shfl_xor_sync(0xffffffffu, s, off);
            if (lane == 0) alf[w] = s;
        }
        __syncthreads();

        if (tid < 256) {
            #pragma unroll
            for (int l = 0; l < LT; l++) {
                float a = alf[l];
                float2 fv = *(const float2*)(Fs + l * 1024 + half * 512 + 2 * tid);
                vacc.x += a * fv.x;
                vacc.y += a * fv.y;
            }
        }
        __syncthreads();
    }

    if (tid < 256) {
        uint32_t hi, lo;
        split2(vacc, hi, lo);
        int p = half * 256 + tid;
        vout[(size_t)n * 1536 + pair_slot(p)] = make_uint2(hi, lo);
    }
}

// ---------------- the persistent loop kernel --------------------------------
__global__ __launch_bounds__(1024) void persist(const float* __restrict__ img,
                                                float* __restrict__ out)
{
    extern __shared__ float smem[];
    int barn = 0;

    for (int t = 0; t < TT; t++) {
        const int cur = t & 1;
        const uint4* catC = g_cat[cur];
        const uint4* catP = g_cat[1 - cur];

        cell_phase(1, t, catP + 256, 768, g_w1p, 256, 8,
                   (uint2*)g_cat[cur] + 512, 1536, g_c1, g_h1f, smem);
        barn++; grid_bar(GRID * barn);

        attn_phase(img, (uint2*)g_cat[cur], smem);
        barn++; grid_bar(GRID * barn);

        cell_phase(2, t, catC, 768, g_wcat, 768, 24,
                   (uint2*)g_cat[1 - cur] + 1024, 1536, g_c2, out, smem);
    }
}

// ---------------- launch -----------------------------------------------------
extern "C" void kernel_launch(void* const* d_in, const int* in_sizes, int n_in,
                              void* d_out, int out_size)
{
    const int*   inputs = (const int*)  d_in[0];
    const float* img    = (const float*)d_in[1];
    const float* emb    = (const float*)d_in[2];
    const float* w_ih1  = (const float*)d_in[3];
    const float* w_hh1  = (const float*)d_in[4];
    const float* b_ih1  = (const float*)d_in[5];
    const float* b_hh1  = (const float*)d_in[6];
    const float* w_ih2  = (const float*)d_in[7];
    const float* w_hh2  = (const float*)d_in[8];
    const float* b_ih2  = (const float*)d_in[9];
    const float* b_hh2  = (const float*)d_in[10];
    float* out = (float*)d_out;
    (void)in_sizes; (void)n_in; (void)out_size;

    const int SMEM_BYTES = (LT * 1024 + 1024 + LT) * 4;   // 118896 (>= 69632 red)

    static bool init = false;
    if (!init) {
        cudaFuncSetAttribute(persist, cudaFuncAttributeMaxDynamicSharedMemorySize,
                             SMEM_BYTES);
        init = true;
    }

    setup_w<<<40960, 256>>>(w_ih1, w_hh1, w_ih2, w_hh2);
    setup_misc<<<4624, 256>>>(inputs, emb, b_ih1, b_hh1, b_ih2, b_hh2);
    mma_x1<<<dim3(32, 16), 1024>>>();
    persist<<<GRID, 1024, SMEM_BYTES>>>(img, out);
}

// round 15
// speedup vs baseline: 1.0497x; 1.0497x over previous
#include <cuda_runtime.h>
#include <cuda_bf16.h>
#include <stdint.h>
#include <math.h>
#include <string.h>

#define BN 64
#define TT 32
#define HD 1024
#define LL 196
#define LT 28            // attention tile rows
#define GRID 128

// ---------------- device scratch --------------------------------------------
__device__ uint4 g_w0p[(size_t)4096 * 256];      // w_ih1 (K=1024), for X1
__device__ uint4 g_w1p[(size_t)4096 * 256];      // w_hh1 (K=1024), cell1
__device__ uint4 g_wcat[(size_t)4096 * 768];     // [w_ih2 | w_hh2] (K=3072), cell2
__device__ uint4 g_cat[2][(size_t)BN * 768];     // [vatt | h1 | h2] A-records
__device__ uint4 g_xp[(size_t)2048 * 256];       // embedded inputs (K=1024 records)
__device__ float g_X1p[(size_t)2048 * 4096];     // x@w_ih1^T + biases (fp32, permuted)
__device__ float g_h1f[BN * HD];
__device__ float g_c1[BN * HD], g_c2[BN * HD];
__device__ float g_bs1[4096], g_bs2[4096];
__device__ int   g_bar_count;

__device__ __forceinline__ float sigf(float x) { return 1.0f / (1.0f + expf(-x)); }

__device__ __forceinline__ uint32_t bfbits(__nv_bfloat16 h) {
    unsigned short s; memcpy(&s, &h, 2); return (uint32_t)s;
}

__device__ __forceinline__ int pair_slot(int p) {
    int ks = p >> 3, w = p & 7;
    return ks * 8 + ((w & 3) << 1) + (w >> 2);
}

__device__ __forceinline__ void split2(float2 v, uint32_t& hi, uint32_t& lo) {
    __nv_bfloat16 h0 = __float2bfloat16(v.x);
    __nv_bfloat16 h1 = __float2bfloat16(v.y);
    __nv_bfloat16 l0 = __float2bfloat16(v.x - __bfloat162float(h0));
    __nv_bfloat16 l1 = __float2bfloat16(v.y - __bfloat162float(h1));
    hi = bfbits(h0) | (bfbits(h1) << 16);
    lo = bfbits(l0) | (bfbits(l1) << 16);
}

__device__ __forceinline__ void mma_bf16(float c[4],
    uint32_t a0, uint32_t a1, uint32_t a2, uint32_t a3,
    uint32_t b0, uint32_t b1)
{
    asm volatile(
        "mma.sync.aligned.m16n8k16.row.col.f32.bf16.bf16.f32 "
        "{%0,%1,%2,%3}, {%4,%5,%6,%7}, {%8,%9}, {%0,%1,%2,%3};"
        : "+f"(c[0]), "+f"(c[1]), "+f"(c[2]), "+f"(c[3])
        : "r"(a0), "r"(a1), "r"(a2), "r"(a3), "r"(b0), "r"(b1));
}

// ---------------- software grid barrier (all 128 blocks resident) -----------
__device__ __forceinline__ void grid_bar(int target) {
    __syncthreads();
    if (threadIdx.x == 0) {
        __threadfence();
        atomicAdd(&g_bar_count, 1);
        while (*(volatile int*)&g_bar_count < target) __nanosleep(64);
    }
    __syncthreads();
}

// ---------------- setup #0: all weight conversion ---------------------------
__device__ __forceinline__ void conv_one(const float* __restrict__ w,
                                         uint2* __restrict__ dst,
                                         int Kw, int lg,
                                         int dst_pit2, int ks_off2, int idx) {
    int j  = idx >> lg;
    int kp = idx & ((1 << lg) - 1);
    int src = (j & 3) * 1024 + (j >> 2);               // gate-interleave perm
    float v0 = w[(size_t)src * Kw + 2 * kp];
    float v1 = w[(size_t)src * Kw + 2 * kp + 1];
    uint32_t hi, lo;
    split2(make_float2(v0, v1), hi, lo);
    int ks = kp >> 3, qp = kp & 3, half = (kp >> 2) & 1;
    dst[(size_t)j * dst_pit2 + ks_off2 + ks * 8 + qp * 2 + half] = make_uint2(hi, lo);
}

__global__ __launch_bounds__(256) void setup_w(
    const float* __restrict__ w_ih1, const float* __restrict__ w_hh1,
    const float* __restrict__ w_ih2, const float* __restrict__ w_hh2)
{
    int b = blockIdx.x, tid = threadIdx.x;
    if (b < 8192)
        conv_one(w_ih1, (uint2*)g_w0p, 1024, 9, 512, 0, b * 256 + tid);
    else if (b < 16384)
        conv_one(w_hh1, (uint2*)g_w1p, 1024, 9, 512, 0, (b - 8192) * 256 + tid);
    else if (b < 32768)
        conv_one(w_ih2, (uint2*)g_wcat, 2048, 10, 1536, 0, (b - 16384) * 256 + tid);
    else
        conv_one(w_hh2, (uint2*)g_wcat, 1024, 9, 1536, 1024, (b - 32768) * 256 + tid);
}

// ---------------- setup #1: zero, bias prep, gather+split, barrier reset ----
__global__ __launch_bounds__(256) void setup_misc(
    const int* __restrict__ inp, const float* __restrict__ emb,
    const float* __restrict__ b_ih1, const float* __restrict__ b_hh1,
    const float* __restrict__ b_ih2, const float* __restrict__ b_hh2)
{
    int b = blockIdx.x, tid = threadIdx.x;
    if (b == 0 && tid == 0) g_bar_count = 0;
    if (b < 384) {
        int i = b * 256 + tid;
        ((uint4*)g_cat)[i] = make_uint4(0u, 0u, 0u, 0u);
    } else if (b < 512) {
        int i = (b - 384) * 256 + tid;
        if (i < 16384) ((float4*)g_c1)[i] = make_float4(0.f, 0.f, 0.f, 0.f);
        else ((float4*)g_c2)[i - 16384] = make_float4(0.f, 0.f, 0.f, 0.f);
    } else if (b < 528) {
        int j = (b - 512) * 256 + tid;
        if (j < 4096) {
            int src = (j & 3) * 1024 + (j >> 2);
            g_bs1[j] = b_ih1[src] + b_hh1[src];
            g_bs2[j] = b_ih2[src] + b_hh2[src];
        }
    } else {
        int idx = (b - 528) * 256 + tid;
        int row = idx >> 9;
        int p   = idx & 511;
        int tok = inp[row];
        float v0 = emb[(size_t)tok * 1024 + 2 * p];
        float v1 = emb[(size_t)tok * 1024 + 2 * p + 1];
        uint32_t hi, lo;
        split2(make_float2(v0, v1), hi, lo);
        ((uint2*)g_xp)[(size_t)row * 512 + pair_slot(p)] = make_uint2(hi, lo);
    }
}

// ---------------- X1 GEMM (R13 shape, pass-major MMA interleave) ------------
__global__ __launch_bounds__(128) void mma_x1() {
    const int lane = threadIdx.x & 31;
    const int warp = threadIdx.x >> 5;
    const int slab = blockIdx.x * 32;
    const int rbase = blockIdx.y * 64;
    const int r_lo = warp * 16 + (lane >> 2);
    const int qpair = lane & 3;
    const int qk = qpair * 2;
    const int qp = lane & 3;

    float c[4][4] = {};

    const uint4* A0 = g_xp + (size_t)(rbase + r_lo) * 256;
    const uint4* A1 = g_xp + (size_t)(rbase + r_lo + 8) * 256;
    const uint4* Wb = g_w0p + (size_t)(slab + (lane >> 2)) * 256;

    for (int ks = 0; ks < 64; ks++) {
        uint4 q0 = A0[ks * 4 + qpair];
        uint4 q1 = A1[ks * 4 + qpair];
        uint4 B0 = Wb[(size_t)0 * 8 * 256 + ks * 4 + qp];
        uint4 B1 = Wb[(size_t)1 * 8 * 256 + ks * 4 + qp];
        uint4 B2 = Wb[(size_t)2 * 8 * 256 + ks * 4 + qp];
        uint4 B3 = Wb[(size_t)3 * 8 * 256 + ks * 4 + qp];
        // pass 0: A-hi x B-hi
        mma_bf16(c[0], q0.x, q1.x, q0.z, q1.z, B0.x, B0.z);
        mma_bf16(c[1], q0.x, q1.x, q0.z, q1.z, B1.x, B1.z);
        mma_bf16(c[2], q0.x, q1.x, q0.z, q1.z, B2.x, B2.z);
        mma_bf16(c[3], q0.x, q1.x, q0.z, q1.z, B3.x, B3.z);
        // pass 1: A-hi x B-lo
        mma_bf16(c[0], q0.x, q1.x, q0.z, q1.z, B0.y, B0.w);
        mma_bf16(c[1], q0.x, q1.x, q0.z, q1.z, B1.y, B1.w);
        mma_bf16(c[2], q0.x, q1.x, q0.z, q1.z, B2.y, B2.w);
        mma_bf16(c[3], q0.x, q1.x, q0.z, q1.z, B3.y, B3.w);
        // pass 2: A-lo x B-hi
        mma_bf16(c[0], q0.y, q1.y, q0.w, q1.w, B0.x, B0.z);
        mma_bf16(c[1], q0.y, q1.y, q0.w, q1.w, B1.x, B1.z);
        mma_bf16(c[2], q0.y, q1.y, q0.w, q1.w, B2.x, B2.z);
        mma_bf16(c[3], q0.y, q1.y, q0.w, q1.w, B3.x, B3.z);
    }

    #pragma unroll
    for (int tl = 0; tl < 4; tl++) {
        int j0 = slab + tl * 8 + qk;
        float2 bs = *(const float2*)(g_bs1 + j0);
        int row0 = rbase + r_lo;
        *(float2*)(g_X1p + (size_t)row0 * 4096 + j0) =
            make_float2(c[tl][0] + bs.x, c[tl][1] + bs.y);
        *(float2*)(g_X1p + (size_t)(row0 + 8) * 4096 + j0) =
            make_float2(c[tl][2] + bs.x, c[tl][3] + bs.y);
    }
}

// ---------------- cell phase (pass-major MMA interleave) --------------------
__device__ __forceinline__ void cell_phase(
    int mode, int t,
    const uint4* __restrict__ A, int a_pit,
    const uint4* __restrict__ W, int w_pit, int nits,
    uint2* __restrict__ hout, int h_pit,
    float* __restrict__ c_state, float* __restrict__ fout,
    float* red)
{
    #define RED(ksl, wr, ln, a) red[(((ksl) * 4 + (wr)) * 32 + (ln)) * 17 + (a)]
    const int lane   = threadIdx.x & 31;
    const int warp   = threadIdx.x >> 5;
    const int kslice = warp >> 2;
    const int wr     = warp & 3;
    const int slab   = blockIdx.x * 32;
    const int r_lo   = wr * 16 + (lane >> 2);
    const int qpair  = lane & 3;
    const int qk = qpair * 2;
    const int qp = lane & 3;

    float c[4][4] = {};

    const uint4* A0 = A + (size_t)r_lo * a_pit;
    const uint4* A1 = A + (size_t)(r_lo + 8) * a_pit;
    const uint4* Wb = W + (size_t)(slab + (lane >> 2)) * w_pit;
    const size_t wstep = (size_t)8 * w_pit;
    const int ks0 = kslice * nits;

    #pragma unroll 4
    for (int it = 0; it < nits; it++) {
        const int ks = ks0 + it;
        uint4 q0 = __ldcg(&A0[ks * 4 + qpair]);
        uint4 q1 = __ldcg(&A1[ks * 4 + qpair]);
        uint4 B0 = Wb[0 * wstep + ks * 4 + qp];
        uint4 B1 = Wb[1 * wstep + ks * 4 + qp];
        uint4 B2 = Wb[2 * wstep + ks * 4 + qp];
        uint4 B3 = Wb[3 * wstep + ks * 4 + qp];
        // pass 0: A-hi x B-hi
        mma_bf16(c[0], q0.x, q1.x, q0.z, q1.z, B0.x, B0.z);
        mma_bf16(c[1], q0.x, q1.x, q0.z, q1.z, B1.x, B1.z);
        mma_bf16(c[2], q0.x, q1.x, q0.z, q1.z, B2.x, B2.z);
        mma_bf16(c[3], q0.x, q1.x, q0.z, q1.z, B3.x, B3.z);
        // pass 1: A-hi x B-lo
        mma_bf16(c[0], q0.x, q1.x, q0.z, q1.z, B0.y, B0.w);
        mma_bf16(c[1], q0.x, q1.x, q0.z, q1.z, B1.y, B1.w);
        mma_bf16(c[2], q0.x, q1.x, q0.z, q1.z, B2.y, B2.w);
        mma_bf16(c[3], q0.x, q1.x, q0.z, q1.z, B3.y, B3.w);
        // pass 2: A-lo x B-hi
        mma_bf16(c[0], q0.y, q1.y, q0.w, q1.w, B0.x, B0.z);
        mma_bf16(c[1], q0.y, q1.y, q0.w, q1.w, B1.x, B1.z);
        mma_bf16(c[2], q0.y, q1.y, q0.w, q1.w, B2.x, B2.z);
        mma_bf16(c[3], q0.y, q1.y, q0.w, q1.w, B3.x, B3.z);
    }

    __syncthreads();
    #pragma unroll
    for (int tl = 0; tl < 4; tl++)
        #pragma unroll
        for (int i = 0; i < 4; i++)
            RED(kslice, wr, lane, tl * 4 + i) = c[tl][i];
    __syncthreads();

    if (warp < 4) {
        #pragma unroll
        for (int tl = 0; tl < 4; tl++)
            #pragma unroll
            for (int i = 0; i < 4; i++) {
                float v = 0.f;
                #pragma unroll
                for (int ksl = 0; ksl < 8; ksl++)
                    v += RED(ksl, wr, lane, tl * 4 + i);
                c[tl][i] = v;
            }

        const bool has_if = ((lane & 1) == 0);
        const int d = (slab >> 2);
        const int pbase = blockIdx.x * 4;

        #pragma unroll
        for (int tl = 0; tl < 4; tl++) {
            int j0 = slab + tl * 8 + qk;
            float x0, x1, x2, x3;
            if (mode == 1) {
                const float* x1p = g_X1p + (size_t)(t * 64 + r_lo) * 4096 + j0;
                float2 aL = *(const float2*)x1p;
                float2 aH = *(const float2*)(x1p + 8 * 4096);
                x0 = c[tl][0] + aL.x; x1 = c[tl][1] + aL.y;
                x2 = c[tl][2] + aH.x; x3 = c[tl][3] + aH.y;
            } else {
                float2 bs = *(const float2*)(g_bs2 + j0);
                x0 = c[tl][0] + bs.x; x1 = c[tl][1] + bs.y;
                x2 = c[tl][2] + bs.x; x3 = c[tl][3] + bs.y;
            }
            float y0 = __shfl_xor_sync(0xffffffffu, x0, 1);
            float y1 = __shfl_xor_sync(0xffffffffu, x1, 1);
            float y2 = __shfl_xor_sync(0xffffffffu, x2, 1);
            float y3 = __shfl_xor_sync(0xffffffffu, x3, 1);

            if (has_if) {
                int dd = d + tl * 2 + ((lane & 3) >> 1);
                int pair = pbase + tl;
                #pragma unroll
                for (int rr = 0; rr < 2; rr++) {
                    float iv = rr ? x2 : x0;
                    float fv = rr ? x3 : x1;
                    float gv = rr ? y2 : y0;
                    float ov = rr ? y3 : y1;
                    int n = r_lo + rr * 8;
                    int idx = n * 1024 + dd;
                    float ig = sigf(iv), fg = sigf(fv);
                    float gg = tanhf(gv), og = sigf(ov);
                    float cn = fg * c_state[idx] + ig * gg;
                    c_state[idx] = cn;
                    float hn = og * tanhf(cn);
                    __nv_bfloat16 hh = __float2bfloat16(hn);
                    uint32_t hib = bfbits(hh);
                    uint32_t lob = bfbits(__float2bfloat16(hn - __bfloat162float(hh)));
                    uint32_t myv = hib | (lob << 16);
                    uint32_t ov2 = __shfl_xor_sync(0x55555555u, myv, 2);
                    if ((lane & 3) == 0) {
                        uint2 w;
                        w.x = (myv & 0xffffu) | ((ov2 & 0xffffu) << 16);
                        w.y = (myv >> 16) | (ov2 & 0xffff0000u);
                        hout[(size_t)n * h_pit + pair_slot(pair)] = w;
                    }
                    if (mode == 1) fout[idx] = hn;
                    else fout[(size_t)(t * 64 + n) * 1024 + dd] = hn;
                }
            }
        }
    }
    #undef RED
}

// ---------------- attention phase (block pair: n = bid>>1, d-half = bid&1) --
__device__ __forceinline__ void attn_phase(const float* __restrict__ img,
                                           uint2* __restrict__ vout,
                                           float* smem)
{
    float* Fs  = smem;                 // LT * 1024
    float* h1s = smem + LT * 1024;     // 1024
    float* alf = h1s + 1024;           // LT

    const int n    = blockIdx.x >> 1;
    const int half = blockIdx.x & 1;
    const int tid  = threadIdx.x;
    const int w    = tid >> 5;
    const int lane = tid & 31;

    h1s[tid] = __ldcg(&g_h1f[(size_t)n * 1024 + tid]);

    const float4* base = (const float4*)(img + (size_t)n * LL * 1024);

    float4 stage[7];
    #pragma unroll
    for (int u = 0; u < 7; u++)
        stage[u] = base[tid + 1024 * u];

    float2 vacc = make_float2(0.f, 0.f);
    __syncthreads();

    for (int tb = 0; tb < LL; tb += LT) {
        #pragma unroll
        for (int u = 0; u < 7; u++)
            ((float4*)Fs)[tid + 1024 * u] = stage[u];
        __syncthreads();

        if (tb + LT < LL) {
            const float4* nb = base + (size_t)(tb + LT) * 256;
            #pragma unroll
            for (int u = 0; u < 7; u++)
                stage[u] = nb[tid + 1024 * u];
        }

        if (w < LT) {
            const float* f = Fs + w * 1024;
            float s = 0.f;
            #pragma unroll
            for (int i = 0; i < 8; i++) {
                int dd = i * 128 + lane * 4;
                float4 fv = *(const float4*)(f + dd);
                s += fv.x * h1s[dd] + fv.y * h1s[dd + 1]
                   + fv.z * h1s[dd + 2] + fv.w * h1s[dd + 3];
            }
            #pragma unroll
            for (int off = 16; off; off >>= 1)
                s += __shfl_xor_sync(0xffffffffu, s, off);
            if (lane == 0) alf[w] = s;
        }
        __syncthreads();

        if (tid < 256) {
            #pragma unroll
            for (int l = 0; l < LT; l++) {
                float a = alf[l];
                float2 fv = *(const float2*)(Fs + l * 1024 + half * 512 + 2 * tid);
                vacc.x += a * fv.x;
                vacc.y += a * fv.y;
            }
        }
        __syncthreads();
    }

    if (tid < 256) {
        uint32_t hi, lo;
        split2(vacc, hi, lo);
        int p = half * 256 + tid;
        vout[(size_t)n * 1536 + pair_slot(p)] = make_uint2(hi, lo);
    }
}

// ---------------- the persistent loop kernel --------------------------------
__global__ __launch_bounds__(1024) void persist(const float* __restrict__ img,
                                                float* __restrict__ out)
{
    extern __shared__ float smem[];
    int barn = 0;

    for (int t = 0; t < TT; t++) {
        const int cur = t & 1;
        const uint4* catC = g_cat[cur];
        const uint4* catP = g_cat[1 - cur];

        cell_phase(1, t, catP + 256, 768, g_w1p, 256, 8,
                   (uint2*)g_cat[cur] + 512, 1536, g_c1, g_h1f, smem);
        barn++; grid_bar(GRID * barn);

        attn_phase(img, (uint2*)g_cat[cur], smem);
        barn++; grid_bar(GRID * barn);

        cell_phase(2, t, catC, 768, g_wcat, 768, 24,
                   (uint2*)g_cat[1 - cur] + 1024, 1536, g_c2, out, smem);
    }
}

// ---------------- launch -----------------------------------------------------
extern "C" void kernel_launch(void* const* d_in, const int* in_sizes, int n_in,
                              void* d_out, int out_size)
{
    const int*   inputs = (const int*)  d_in[0];
    const float* img    = (const float*)d_in[1];
    const float* emb    = (const float*)d_in[2];
    const float* w_ih1  = (const float*)d_in[3];
    const float* w_hh1  = (const float*)d_in[4];
    const float* b_ih1  = (const float*)d_in[5];
    const float* b_hh1  = (const float*)d_in[6];
    const float* w_ih2  = (const float*)d_in[7];
    const float* w_hh2  = (const float*)d_in[8];
    const float* b_ih2  = (const float*)d_in[9];
    const float* b_hh2  = (const float*)d_in[10];
    float* out = (float*)d_out;
    (void)in_sizes; (void)n_in; (void)out_size;

    const int SMEM_BYTES = (LT * 1024 + 1024 + LT) * 4;   // 118896 (>= 69632 red)

    static bool init = false;
    if (!init) {
        cudaFuncSetAttribute(persist, cudaFuncAttributeMaxDynamicSharedMemorySize,
                             SMEM_BYTES);
        init = true;
    }

    setup_w<<<40960, 256>>>(w_ih1, w_hh1, w_ih2, w_hh2);
    setup_misc<<<4624, 256>>>(inputs, emb, b_ih1, b_hh1, b_ih2, b_hh2);
    mma_x1<<<dim3(128, 32), 128>>>();
    persist<<<GRID, 1024, SMEM_BYTES>>>(img, out);
}